// round 2
// baseline (speedup 1.0000x reference)
#include <cuda_runtime.h>
#include <math.h>

// ---------------- problem constants ----------------
#define L_TOT   13294          // 10000 + 2500 + 625 + 169
#define BATCH   4
#define MROWS   (BATCH * L_TOT)   // 53176
#define DMODEL  256
#define DFFN    1024
#define NLAYERS_C 6
#define NHEADS  8
#define HDIM    32

// ---------------- device scratch (static, allowed) ----------------
__device__ float g_src [MROWS * DMODEL];
__device__ float g_pos [MROWS * DMODEL];
__device__ float g_q   [MROWS * DMODEL];
__device__ float g_val [MROWS * DMODEL];
__device__ float g_off [MROWS * DMODEL];
__device__ float g_aw  [MROWS * 128];
__device__ float g_attn[MROWS * DMODEL];
__device__ float g_tmp [MROWS * DMODEL];
__device__ float g_h   [MROWS * DFFN];

// ---------------- flatten: (B,D,H,W) -> (B, L, D), pos += level_embed ----------------
__global__ void flatten_kernel(const float* __restrict__ s0, const float* __restrict__ s1,
                               const float* __restrict__ s2, const float* __restrict__ s3,
                               const float* __restrict__ p0, const float* __restrict__ p1,
                               const float* __restrict__ p2, const float* __restrict__ p3,
                               const float* __restrict__ lvl_emb)
{
    long long idx = (long long)blockIdx.x * blockDim.x + threadIdx.x;
    const long long tot = (long long)MROWS * DMODEL;
    if (idx >= tot) return;
    int d = (int)(idx & 255);
    int m = (int)(idx >> 8);
    int b = m / L_TOT;
    int n = m - b * L_TOT;
    int lvl, hw, HW;
    const float *sp, *pp;
    if (n < 10000)      { lvl = 0; hw = n;         HW = 10000; sp = s0; pp = p0; }
    else if (n < 12500) { lvl = 1; hw = n - 10000; HW = 2500;  sp = s1; pp = p1; }
    else if (n < 13125) { lvl = 2; hw = n - 12500; HW = 625;   sp = s2; pp = p2; }
    else                { lvl = 3; hw = n - 13125; HW = 169;   sp = s3; pp = p3; }
    size_t sidx = ((size_t)b * DMODEL + d) * HW + hw;
    g_src[idx] = __ldg(sp + sidx);
    g_pos[idx] = __ldg(pp + sidx) + __ldg(lvl_emb + lvl * DMODEL + d);
}

// ---------------- q = src + pos ----------------
__global__ void add_q_kernel()
{
    long long idx = (long long)blockIdx.x * blockDim.x + threadIdx.x;
    const long long tot = (long long)MROWS * DMODEL;
    if (idx >= tot) return;
    g_q[idx] = g_src[idx] + g_pos[idx];
}

// ---------------- fp32 tiled GEMM: C[M,N] = A[M,K] @ W[K,N] + bias (opt ReLU) -------
// BM=BN=64, BK=16, 256 threads, 4x4 per thread.
template<bool RELU>
__global__ __launch_bounds__(256)
void gemm_bias_kernel(const float* __restrict__ A, const float* __restrict__ Wt,
                      const float* __restrict__ bias, float* __restrict__ C,
                      int Mr, int K, int N)
{
    __shared__ float As[16][64];
    __shared__ float Bs[16][64];
    const int tid  = threadIdx.x;
    const int tx   = tid & 15;
    const int ty   = tid >> 4;
    const int row0 = blockIdx.x * 64;
    const int col0 = blockIdx.y * 64;

    float acc[4][4];
    #pragma unroll
    for (int i = 0; i < 4; i++)
        #pragma unroll
        for (int j = 0; j < 4; j++) acc[i][j] = 0.f;

    const int ar  = tid >> 2;        // 0..63
    const int ac4 = (tid & 3) * 4;   // 0,4,8,12
    const int br  = tid >> 4;        // 0..15
    const int bc4 = (tid & 15) * 4;  // 0..60

    const bool arow_ok = (row0 + ar) < Mr;
    const float* aptr = A + (size_t)(row0 + ar) * K + ac4;
    const float* bptr = Wt + (size_t)br * N + col0 + bc4;

    for (int k0 = 0; k0 < K; k0 += 16) {
        float4 av = make_float4(0.f, 0.f, 0.f, 0.f);
        if (arow_ok) av = *reinterpret_cast<const float4*>(aptr + k0);
        As[ac4 + 0][ar] = av.x;
        As[ac4 + 1][ar] = av.y;
        As[ac4 + 2][ar] = av.z;
        As[ac4 + 3][ar] = av.w;
        float4 bv = *reinterpret_cast<const float4*>(bptr + (size_t)k0 * N);
        *reinterpret_cast<float4*>(&Bs[br][bc4]) = bv;
        __syncthreads();
        #pragma unroll
        for (int kk = 0; kk < 16; kk++) {
            float a[4], b[4];
            *reinterpret_cast<float4*>(a) = *reinterpret_cast<const float4*>(&As[kk][ty * 4]);
            *reinterpret_cast<float4*>(b) = *reinterpret_cast<const float4*>(&Bs[kk][tx * 4]);
            #pragma unroll
            for (int i = 0; i < 4; i++)
                #pragma unroll
                for (int j = 0; j < 4; j++)
                    acc[i][j] = fmaf(a[i], b[j], acc[i][j]);
        }
        __syncthreads();
    }

    #pragma unroll
    for (int i = 0; i < 4; i++) {
        int row = row0 + ty * 4 + i;
        if (row >= Mr) continue;
        #pragma unroll
        for (int j = 0; j < 4; j++) {
            int col = col0 + tx * 4 + j;
            float v = acc[i][j] + __ldg(bias + col);
            if (RELU) v = fmaxf(v, 0.f);
            C[(size_t)row * N + col] = v;
        }
    }
}

// ---------------- deformable attention sampling (one warp per (b,q,head)) -----------
__global__ void deform_kernel(const float* __restrict__ value,
                              const float* __restrict__ off,
                              const float* __restrict__ aw,
                              float* __restrict__ out)
{
    int gw = (int)((blockIdx.x * blockDim.x + threadIdx.x) >> 5);
    if (gw >= MROWS * NHEADS) return;
    int lane = threadIdx.x & 31;
    int h = gw & 7;
    int m = gw >> 3;
    int b = m / L_TOT;
    int q = m - b * L_TOT;

    // reference point from the query's own level grid
    float ref_x, ref_y;
    {
        int idx, Wl, Hl;
        if (q < 10000)      { idx = q;         Wl = 100; Hl = 100; }
        else if (q < 12500) { idx = q - 10000; Wl = 50;  Hl = 50;  }
        else if (q < 13125) { idx = q - 12500; Wl = 25;  Hl = 25;  }
        else                { idx = q - 13125; Wl = 13;  Hl = 13;  }
        int yy = idx / Wl, xx = idx - yy * Wl;
        ref_x = (xx + 0.5f) / (float)Wl;
        ref_y = (yy + 0.5f) / (float)Hl;
    }

    // softmax over 16 attention logits (redundant per lane, cheap)
    const float* awp = aw + (size_t)m * 128 + h * 16;
    float e[16];
    float mx = -1e30f;
    #pragma unroll
    for (int i = 0; i < 16; i++) { e[i] = __ldg(awp + i); mx = fmaxf(mx, e[i]); }
    float ssum = 0.f;
    #pragma unroll
    for (int i = 0; i < 16; i++) { e[i] = __expf(e[i] - mx); ssum += e[i]; }
    float inv = 1.f / ssum;

    const float* offp  = off + (size_t)m * 256 + h * 32;
    const float* vbase = value + (size_t)b * L_TOT * 256 + h * 32 + lane;

    const int Ws[4]     = {100, 50, 25, 13};
    const int Hs[4]     = {100, 50, 25, 13};
    const int starts[4] = {0, 10000, 12500, 13125};

    float acc = 0.f;
    #pragma unroll
    for (int l = 0; l < 4; l++) {
        const int   Wl = Ws[l], Hl = Hs[l], st = starts[l];
        const float fW = (float)Wl, fH = (float)Hl;
        #pragma unroll
        for (int p = 0; p < 4; p++) {
            float ox = __ldg(offp + l * 8 + p * 2);
            float oy = __ldg(offp + l * 8 + p * 2 + 1);
            float px = ref_x * fW + ox - 0.5f;
            float py = ref_y * fH + oy - 0.5f;
            float x0f = floorf(px), y0f = floorf(py);
            float wx1 = px - x0f, wy1 = py - y0f;
            int x0 = (int)x0f, y0 = (int)y0f;
            float wgt = e[l * 4 + p] * inv;
            #pragma unroll
            for (int t = 0; t < 4; t++) {
                int xi = x0 + (t & 1);
                int yi = y0 + (t >> 1);
                float w = ((t & 1) ? wx1 : 1.f - wx1) * ((t >> 1) ? wy1 : 1.f - wy1);
                if (xi >= 0 && xi < Wl && yi >= 0 && yi < Hl && w != 0.f) {
                    acc = fmaf(wgt * w,
                               __ldg(vbase + (size_t)(st + yi * Wl + xi) * 256),
                               acc);
                }
            }
        }
    }
    out[(size_t)m * 256 + h * 32 + lane] = acc;
}

// ---------------- fused residual add + LayerNorm (one warp per row) ----------------
__global__ void add_ln_kernel(const float* __restrict__ X, const float* __restrict__ R,
                              const float* __restrict__ w, const float* __restrict__ b,
                              float* __restrict__ out)
{
    int row = (int)((blockIdx.x * blockDim.x + threadIdx.x) >> 5);
    if (row >= MROWS) return;
    int lane = threadIdx.x & 31;
    const float* x = X + (size_t)row * DMODEL;
    const float* r = R + (size_t)row * DMODEL;
    float v[8];
    float s = 0.f;
    #pragma unroll
    for (int j = 0; j < 8; j++) {
        int c = lane + j * 32;
        v[j] = x[c] + r[c];
        s += v[j];
    }
    #pragma unroll
    for (int o = 16; o > 0; o >>= 1) s += __shfl_xor_sync(0xFFFFFFFFu, s, o);
    float mean = s * (1.f / 256.f);
    float qv = 0.f;
    #pragma unroll
    for (int j = 0; j < 8; j++) { float d = v[j] - mean; qv += d * d; }
    #pragma unroll
    for (int o = 16; o > 0; o >>= 1) qv += __shfl_xor_sync(0xFFFFFFFFu, qv, o);
    float invs = rsqrtf(qv * (1.f / 256.f) + 1e-5f);
    #pragma unroll
    for (int j = 0; j < 8; j++) {
        int c = lane + j * 32;
        out[(size_t)row * DMODEL + c] = (v[j] - mean) * invs * __ldg(w + c) + __ldg(b + c);
    }
}

// ---------------- output write: src then level_start_index (as floats) -------------
__global__ void write_out_kernel(float* __restrict__ out, int n)
{
    long long i = (long long)blockIdx.x * blockDim.x + threadIdx.x;
    if (i >= n) return;
    const long long tot = (long long)MROWS * DMODEL;
    if (i < tot) {
        out[i] = g_src[i];
    } else {
        int k = (int)(i - tot);
        float st;
        switch (k) {
            case 0: st = 0.f;      break;
            case 1: st = 10000.f;  break;
            case 2: st = 12500.f;  break;
            case 3: st = 13125.f;  break;
            default: st = 0.f;     break;
        }
        out[i] = st;
    }
}

// ---------------- host launch ----------------
extern "C" void kernel_launch(void* const* d_in, const int* in_sizes, int n_in,
                              void* d_out, int out_size)
{
    // NOTE: setup_inputs() dict order is INTERLEAVED: src0, pos0, src1, pos1, ...
    const float* s0 = (const float*)d_in[0];
    const float* p0 = (const float*)d_in[1];
    const float* s1 = (const float*)d_in[2];
    const float* p1 = (const float*)d_in[3];
    const float* s2 = (const float*)d_in[4];
    const float* p2 = (const float*)d_in[5];
    const float* s3 = (const float*)d_in[6];
    const float* p3 = (const float*)d_in[7];
    const float* lvl_emb = (const float*)d_in[8];
    const float* so_w = (const float*)d_in[9];
    const float* so_b = (const float*)d_in[10];
    const float* aw_w = (const float*)d_in[11];
    const float* aw_b = (const float*)d_in[12];
    const float* vp_w = (const float*)d_in[13];
    const float* vp_b = (const float*)d_in[14];
    const float* op_w = (const float*)d_in[15];
    const float* op_b = (const float*)d_in[16];
    const float* n1_w = (const float*)d_in[17];
    const float* n1_b = (const float*)d_in[18];
    const float* f1_w = (const float*)d_in[19];
    const float* f1_b = (const float*)d_in[20];
    const float* f2_w = (const float*)d_in[21];
    const float* f2_b = (const float*)d_in[22];
    const float* n2_w = (const float*)d_in[23];
    const float* n2_b = (const float*)d_in[24];

    float *pg_src, *pg_pos, *pg_q, *pg_val, *pg_off, *pg_aw, *pg_attn, *pg_tmp, *pg_h;
    cudaGetSymbolAddress((void**)&pg_src,  g_src);
    cudaGetSymbolAddress((void**)&pg_pos,  g_pos);
    cudaGetSymbolAddress((void**)&pg_q,    g_q);
    cudaGetSymbolAddress((void**)&pg_val,  g_val);
    cudaGetSymbolAddress((void**)&pg_off,  g_off);
    cudaGetSymbolAddress((void**)&pg_aw,   g_aw);
    cudaGetSymbolAddress((void**)&pg_attn, g_attn);
    cudaGetSymbolAddress((void**)&pg_tmp,  g_tmp);
    cudaGetSymbolAddress((void**)&pg_h,    g_h);

    const long long totElem = (long long)MROWS * DMODEL;
    const int ew_grid = (int)((totElem + 255) / 256);

    flatten_kernel<<<ew_grid, 256>>>(s0, s1, s2, s3, p0, p1, p2, p3, lvl_emb);

    const dim3 gemm_blk(256);
    const int mblk = (MROWS + 63) / 64;
    const dim3 grid256(mblk, DMODEL / 64);   // N=256
    const dim3 grid128(mblk, 128 / 64);      // N=128
    const dim3 grid1024(mblk, DFFN / 64);    // N=1024
    const int ln_grid = (MROWS * 32 + 255) / 256;
    const int deform_grid = (MROWS * NHEADS * 32 + 255) / 256;

    for (int i = 0; i < NLAYERS_C; i++) {
        const float* so_wi = so_w + (size_t)i * DMODEL * 256;
        const float* so_bi = so_b + (size_t)i * 256;
        const float* aw_wi = aw_w + (size_t)i * DMODEL * 128;
        const float* aw_bi = aw_b + (size_t)i * 128;
        const float* vp_wi = vp_w + (size_t)i * DMODEL * DMODEL;
        const float* vp_bi = vp_b + (size_t)i * DMODEL;
        const float* op_wi = op_w + (size_t)i * DMODEL * DMODEL;
        const float* op_bi = op_b + (size_t)i * DMODEL;
        const float* f1_wi = f1_w + (size_t)i * DMODEL * DFFN;
        const float* f1_bi = f1_b + (size_t)i * DFFN;
        const float* f2_wi = f2_w + (size_t)i * DFFN * DMODEL;
        const float* f2_bi = f2_b + (size_t)i * DMODEL;

        // value = src @ vp_w + vp_b
        gemm_bias_kernel<false><<<grid256, gemm_blk>>>(pg_src, vp_wi, vp_bi, pg_val,
                                                       MROWS, DMODEL, DMODEL);
        // q = src + pos
        add_q_kernel<<<ew_grid, 256>>>();
        // offsets = q @ so_w + so_b
        gemm_bias_kernel<false><<<grid256, gemm_blk>>>(pg_q, so_wi, so_bi, pg_off,
                                                       MROWS, DMODEL, 256);
        // aw logits = q @ aw_w + aw_b
        gemm_bias_kernel<false><<<grid128, gemm_blk>>>(pg_q, aw_wi, aw_bi, pg_aw,
                                                       MROWS, DMODEL, 128);
        // deformable sampling
        deform_kernel<<<deform_grid, 256>>>(pg_val, pg_off, pg_aw, pg_attn);
        // output proj
        gemm_bias_kernel<false><<<grid256, gemm_blk>>>(pg_attn, op_wi, op_bi, pg_tmp,
                                                       MROWS, DMODEL, DMODEL);
        // src = LN(src + attn_proj)
        add_ln_kernel<<<ln_grid, 256>>>(pg_src, pg_tmp,
                                        n1_w + (size_t)i * DMODEL, n1_b + (size_t)i * DMODEL,
                                        pg_src);
        // h = relu(src @ f1_w + f1_b)
        gemm_bias_kernel<true><<<grid1024, gemm_blk>>>(pg_src, f1_wi, f1_bi, pg_h,
                                                       MROWS, DMODEL, DFFN);
        // tmp = h @ f2_w + f2_b
        gemm_bias_kernel<false><<<grid256, gemm_blk>>>(pg_h, f2_wi, f2_bi, pg_tmp,
                                                       MROWS, DFFN, DMODEL);
        // src = LN(src + ffn)
        add_ln_kernel<<<ln_grid, 256>>>(pg_src, pg_tmp,
                                        n2_w + (size_t)i * DMODEL, n2_b + (size_t)i * DMODEL,
                                        pg_src);
    }

    write_out_kernel<<<(out_size + 255) / 256, 256>>>((float*)d_out, out_size);
}

// round 3
// speedup vs baseline: 1.2147x; 1.2147x over previous
#include <cuda_runtime.h>
#include <math.h>

// ---------------- problem constants ----------------
#define L_TOT   13294          // 10000 + 2500 + 625 + 169
#define BATCH   4
#define MROWS   (BATCH * L_TOT)   // 53176
#define DMODEL  256
#define DFFN    1024
#define NLAYERS_C 6
#define NHEADS  8
#define HDIM    32

// ---------------- device scratch (static, allowed) ----------------
__device__ float g_src [MROWS * DMODEL];
__device__ float g_pos [MROWS * DMODEL];
__device__ float g_q   [MROWS * DMODEL];
__device__ float g_val [MROWS * DMODEL];
__device__ float g_off [MROWS * DMODEL];
__device__ float g_aw  [MROWS * 128];
__device__ float g_attn[MROWS * DMODEL];
__device__ float g_tmp [MROWS * DMODEL];
__device__ float g_h   [MROWS * DFFN];

// ---------------- flatten: (B,D,H,W) -> (B, L, D), pos += level_embed ----------------
__global__ void flatten_kernel(const float* __restrict__ s0, const float* __restrict__ s1,
                               const float* __restrict__ s2, const float* __restrict__ s3,
                               const float* __restrict__ p0, const float* __restrict__ p1,
                               const float* __restrict__ p2, const float* __restrict__ p3,
                               const float* __restrict__ lvl_emb)
{
    long long idx = (long long)blockIdx.x * blockDim.x + threadIdx.x;
    const long long tot = (long long)MROWS * DMODEL;
    if (idx >= tot) return;
    int d = (int)(idx & 255);
    int m = (int)(idx >> 8);
    int b = m / L_TOT;
    int n = m - b * L_TOT;
    int lvl, hw, HW;
    const float *sp, *pp;
    if (n < 10000)      { lvl = 0; hw = n;         HW = 10000; sp = s0; pp = p0; }
    else if (n < 12500) { lvl = 1; hw = n - 10000; HW = 2500;  sp = s1; pp = p1; }
    else if (n < 13125) { lvl = 2; hw = n - 12500; HW = 625;   sp = s2; pp = p2; }
    else                { lvl = 3; hw = n - 13125; HW = 169;   sp = s3; pp = p3; }
    size_t sidx = ((size_t)b * DMODEL + d) * HW + hw;
    g_src[idx] = __ldg(sp + sidx);
    g_pos[idx] = __ldg(pp + sidx) + __ldg(lvl_emb + lvl * DMODEL + d);
}

// ---------------- q = src + pos ----------------
__global__ void add_q_kernel()
{
    long long idx = (long long)blockIdx.x * blockDim.x + threadIdx.x;
    const long long tot = (long long)MROWS * DMODEL;
    if (idx >= tot) return;
    g_q[idx] = g_src[idx] + g_pos[idx];
}

// ---------------- fp32 GEMM: C[M,N] = A[M,K] @ W[K,N] + bias (opt ReLU) ------------
// 128x128 block tile, BK=16, 256 threads, 8x8 per-thread microtile, double-buffered.
template<bool RELU>
__global__ __launch_bounds__(256)
void gemm128_kernel(const float* __restrict__ A, const float* __restrict__ Wt,
                    const float* __restrict__ bias, float* __restrict__ C,
                    int Mr, int K, int N)
{
    __shared__ float As[2][16][128];   // transposed: As[k][m]
    __shared__ float Bs[2][16][128];   // Bs[k][n]

    const int tid  = threadIdx.x;
    const int tx   = tid & 15;          // n-direction (8 cols each)
    const int ty   = tid >> 4;          // m-direction (8 rows each)
    const int row0 = blockIdx.x * 128;
    const int col0 = blockIdx.y * 128;

    // A tile loads: 128x16 = 512 float4; 2 per thread
    const int aRow0 = tid >> 2;          // 0..63
    const int aC4   = (tid & 3) * 4;     // 0,4,8,12
    // B tile loads: 16x128 = 512 float4; 2 per thread
    const int bRow0 = tid >> 5;          // 0..7
    const int bC4   = (tid & 31) * 4;    // 0..124

    const bool aOk0 = (row0 + aRow0)      < Mr;
    const bool aOk1 = (row0 + aRow0 + 64) < Mr;
    const float* aP0 = A + (size_t)(row0 + aRow0)      * K + aC4;
    const float* aP1 = A + (size_t)(row0 + aRow0 + 64) * K + aC4;
    const float* bP0 = Wt + (size_t)bRow0       * N + col0 + bC4;
    const float* bP1 = Wt + (size_t)(bRow0 + 8) * N + col0 + bC4;

    float acc[8][8];
    #pragma unroll
    for (int i = 0; i < 8; i++)
        #pragma unroll
        for (int j = 0; j < 8; j++) acc[i][j] = 0.f;

    const int nt = K >> 4;   // K is a multiple of 16 (256 or 1024)

    float4 av0, av1, bv0, bv1;

    // prologue: load tile 0
    av0 = aOk0 ? *reinterpret_cast<const float4*>(aP0) : make_float4(0,0,0,0);
    av1 = aOk1 ? *reinterpret_cast<const float4*>(aP1) : make_float4(0,0,0,0);
    bv0 = *reinterpret_cast<const float4*>(bP0);
    bv1 = *reinterpret_cast<const float4*>(bP1);
    {
        As[0][aC4 + 0][aRow0] = av0.x;  As[0][aC4 + 1][aRow0] = av0.y;
        As[0][aC4 + 2][aRow0] = av0.z;  As[0][aC4 + 3][aRow0] = av0.w;
        As[0][aC4 + 0][aRow0 + 64] = av1.x;  As[0][aC4 + 1][aRow0 + 64] = av1.y;
        As[0][aC4 + 2][aRow0 + 64] = av1.z;  As[0][aC4 + 3][aRow0 + 64] = av1.w;
        *reinterpret_cast<float4*>(&Bs[0][bRow0][bC4])     = bv0;
        *reinterpret_cast<float4*>(&Bs[0][bRow0 + 8][bC4]) = bv1;
    }
    __syncthreads();

    for (int t = 0; t < nt; t++) {
        const int buf = t & 1;
        // issue global loads for next tile early
        if (t + 1 < nt) {
            const int k0 = (t + 1) << 4;
            av0 = aOk0 ? *reinterpret_cast<const float4*>(aP0 + k0) : make_float4(0,0,0,0);
            av1 = aOk1 ? *reinterpret_cast<const float4*>(aP1 + k0) : make_float4(0,0,0,0);
            bv0 = *reinterpret_cast<const float4*>(bP0 + (size_t)k0 * N);
            bv1 = *reinterpret_cast<const float4*>(bP1 + (size_t)k0 * N);
        }
        // compute on current buffer
        #pragma unroll
        for (int kk = 0; kk < 16; kk++) {
            float a[8], b[8];
            *reinterpret_cast<float4*>(&a[0]) = *reinterpret_cast<const float4*>(&As[buf][kk][ty * 8]);
            *reinterpret_cast<float4*>(&a[4]) = *reinterpret_cast<const float4*>(&As[buf][kk][ty * 8 + 4]);
            *reinterpret_cast<float4*>(&b[0]) = *reinterpret_cast<const float4*>(&Bs[buf][kk][tx * 8]);
            *reinterpret_cast<float4*>(&b[4]) = *reinterpret_cast<const float4*>(&Bs[buf][kk][tx * 8 + 4]);
            #pragma unroll
            for (int i = 0; i < 8; i++)
                #pragma unroll
                for (int j = 0; j < 8; j++)
                    acc[i][j] = fmaf(a[i], b[j], acc[i][j]);
        }
        // stage next tile into the other buffer
        if (t + 1 < nt) {
            const int nb = buf ^ 1;
            As[nb][aC4 + 0][aRow0] = av0.x;  As[nb][aC4 + 1][aRow0] = av0.y;
            As[nb][aC4 + 2][aRow0] = av0.z;  As[nb][aC4 + 3][aRow0] = av0.w;
            As[nb][aC4 + 0][aRow0 + 64] = av1.x;  As[nb][aC4 + 1][aRow0 + 64] = av1.y;
            As[nb][aC4 + 2][aRow0 + 64] = av1.z;  As[nb][aC4 + 3][aRow0 + 64] = av1.w;
            *reinterpret_cast<float4*>(&Bs[nb][bRow0][bC4])     = bv0;
            *reinterpret_cast<float4*>(&Bs[nb][bRow0 + 8][bC4]) = bv1;
        }
        __syncthreads();
    }

    // epilogue: bias (+ReLU), guarded store
    float bvals[8];
    #pragma unroll
    for (int j = 0; j < 8; j++) bvals[j] = __ldg(bias + col0 + tx * 8 + j);

    #pragma unroll
    for (int i = 0; i < 8; i++) {
        const int row = row0 + ty * 8 + i;
        if (row >= Mr) continue;
        float4 o0, o1;
        float v;
        v = acc[i][0] + bvals[0]; o0.x = RELU ? fmaxf(v, 0.f) : v;
        v = acc[i][1] + bvals[1]; o0.y = RELU ? fmaxf(v, 0.f) : v;
        v = acc[i][2] + bvals[2]; o0.z = RELU ? fmaxf(v, 0.f) : v;
        v = acc[i][3] + bvals[3]; o0.w = RELU ? fmaxf(v, 0.f) : v;
        v = acc[i][4] + bvals[4]; o1.x = RELU ? fmaxf(v, 0.f) : v;
        v = acc[i][5] + bvals[5]; o1.y = RELU ? fmaxf(v, 0.f) : v;
        v = acc[i][6] + bvals[6]; o1.z = RELU ? fmaxf(v, 0.f) : v;
        v = acc[i][7] + bvals[7]; o1.w = RELU ? fmaxf(v, 0.f) : v;
        float* cp = C + (size_t)row * N + col0 + tx * 8;
        *reinterpret_cast<float4*>(cp)     = o0;
        *reinterpret_cast<float4*>(cp + 4) = o1;
    }
}

// ---------------- deformable attention sampling (one warp per (b,q,head)) -----------
__global__ void deform_kernel(const float* __restrict__ value,
                              const float* __restrict__ off,
                              const float* __restrict__ aw,
                              float* __restrict__ out)
{
    int gw = (int)((blockIdx.x * blockDim.x + threadIdx.x) >> 5);
    if (gw >= MROWS * NHEADS) return;
    int lane = threadIdx.x & 31;
    int h = gw & 7;
    int m = gw >> 3;
    int b = m / L_TOT;
    int q = m - b * L_TOT;

    // reference point from the query's own level grid
    float ref_x, ref_y;
    {
        int idx, Wl, Hl;
        if (q < 10000)      { idx = q;         Wl = 100; Hl = 100; }
        else if (q < 12500) { idx = q - 10000; Wl = 50;  Hl = 50;  }
        else if (q < 13125) { idx = q - 12500; Wl = 25;  Hl = 25;  }
        else                { idx = q - 13125; Wl = 13;  Hl = 13;  }
        int yy = idx / Wl, xx = idx - yy * Wl;
        ref_x = (xx + 0.5f) / (float)Wl;
        ref_y = (yy + 0.5f) / (float)Hl;
    }

    // softmax over 16 attention logits (redundant per lane, cheap)
    const float* awp = aw + (size_t)m * 128 + h * 16;
    float e[16];
    float mx = -1e30f;
    #pragma unroll
    for (int i = 0; i < 16; i++) { e[i] = __ldg(awp + i); mx = fmaxf(mx, e[i]); }
    float ssum = 0.f;
    #pragma unroll
    for (int i = 0; i < 16; i++) { e[i] = __expf(e[i] - mx); ssum += e[i]; }
    float inv = 1.f / ssum;

    const float* offp  = off + (size_t)m * 256 + h * 32;
    const float* vbase = value + (size_t)b * L_TOT * 256 + h * 32 + lane;

    const int Ws[4]     = {100, 50, 25, 13};
    const int Hs[4]     = {100, 50, 25, 13};
    const int starts[4] = {0, 10000, 12500, 13125};

    float acc = 0.f;
    #pragma unroll
    for (int l = 0; l < 4; l++) {
        const int   Wl = Ws[l], Hl = Hs[l], st = starts[l];
        const float fW = (float)Wl, fH = (float)Hl;
        #pragma unroll
        for (int p = 0; p < 4; p++) {
            float ox = __ldg(offp + l * 8 + p * 2);
            float oy = __ldg(offp + l * 8 + p * 2 + 1);
            float px = ref_x * fW + ox - 0.5f;
            float py = ref_y * fH + oy - 0.5f;
            float x0f = floorf(px), y0f = floorf(py);
            float wx1 = px - x0f, wy1 = py - y0f;
            int x0 = (int)x0f, y0 = (int)y0f;
            float wgt = e[l * 4 + p] * inv;
            #pragma unroll
            for (int t = 0; t < 4; t++) {
                int xi = x0 + (t & 1);
                int yi = y0 + (t >> 1);
                float w = ((t & 1) ? wx1 : 1.f - wx1) * ((t >> 1) ? wy1 : 1.f - wy1);
                if (xi >= 0 && xi < Wl && yi >= 0 && yi < Hl && w != 0.f) {
                    acc = fmaf(wgt * w,
                               __ldg(vbase + (size_t)(st + yi * Wl + xi) * 256),
                               acc);
                }
            }
        }
    }
    out[(size_t)m * 256 + h * 32 + lane] = acc;
}

// ---------------- fused residual add + LayerNorm (one warp per row) ----------------
__global__ void add_ln_kernel(const float* __restrict__ X, const float* __restrict__ R,
                              const float* __restrict__ w, const float* __restrict__ b,
                              float* __restrict__ out)
{
    int row = (int)((blockIdx.x * blockDim.x + threadIdx.x) >> 5);
    if (row >= MROWS) return;
    int lane = threadIdx.x & 31;
    const float* x = X + (size_t)row * DMODEL;
    const float* r = R + (size_t)row * DMODEL;
    float v[8];
    float s = 0.f;
    #pragma unroll
    for (int j = 0; j < 8; j++) {
        int c = lane + j * 32;
        v[j] = x[c] + r[c];
        s += v[j];
    }
    #pragma unroll
    for (int o = 16; o > 0; o >>= 1) s += __shfl_xor_sync(0xFFFFFFFFu, s, o);
    float mean = s * (1.f / 256.f);
    float qv = 0.f;
    #pragma unroll
    for (int j = 0; j < 8; j++) { float d = v[j] - mean; qv += d * d; }
    #pragma unroll
    for (int o = 16; o > 0; o >>= 1) qv += __shfl_xor_sync(0xFFFFFFFFu, qv, o);
    float invs = rsqrtf(qv * (1.f / 256.f) + 1e-5f);
    #pragma unroll
    for (int j = 0; j < 8; j++) {
        int c = lane + j * 32;
        out[(size_t)row * DMODEL + c] = (v[j] - mean) * invs * __ldg(w + c) + __ldg(b + c);
    }
}

// ---------------- output write: src then level_start_index (as floats) -------------
__global__ void write_out_kernel(float* __restrict__ out, int n)
{
    long long i = (long long)blockIdx.x * blockDim.x + threadIdx.x;
    if (i >= n) return;
    const long long tot = (long long)MROWS * DMODEL;
    if (i < tot) {
        out[i] = g_src[i];
    } else {
        int k = (int)(i - tot);
        float st;
        switch (k) {
            case 0: st = 0.f;      break;
            case 1: st = 10000.f;  break;
            case 2: st = 12500.f;  break;
            case 3: st = 13125.f;  break;
            default: st = 0.f;     break;
        }
        out[i] = st;
    }
}

// ---------------- host launch ----------------
extern "C" void kernel_launch(void* const* d_in, const int* in_sizes, int n_in,
                              void* d_out, int out_size)
{
    // NOTE: setup_inputs() dict order is INTERLEAVED: src0, pos0, src1, pos1, ...
    const float* s0 = (const float*)d_in[0];
    const float* p0 = (const float*)d_in[1];
    const float* s1 = (const float*)d_in[2];
    const float* p1 = (const float*)d_in[3];
    const float* s2 = (const float*)d_in[4];
    const float* p2 = (const float*)d_in[5];
    const float* s3 = (const float*)d_in[6];
    const float* p3 = (const float*)d_in[7];
    const float* lvl_emb = (const float*)d_in[8];
    const float* so_w = (const float*)d_in[9];
    const float* so_b = (const float*)d_in[10];
    const float* aw_w = (const float*)d_in[11];
    const float* aw_b = (const float*)d_in[12];
    const float* vp_w = (const float*)d_in[13];
    const float* vp_b = (const float*)d_in[14];
    const float* op_w = (const float*)d_in[15];
    const float* op_b = (const float*)d_in[16];
    const float* n1_w = (const float*)d_in[17];
    const float* n1_b = (const float*)d_in[18];
    const float* f1_w = (const float*)d_in[19];
    const float* f1_b = (const float*)d_in[20];
    const float* f2_w = (const float*)d_in[21];
    const float* f2_b = (const float*)d_in[22];
    const float* n2_w = (const float*)d_in[23];
    const float* n2_b = (const float*)d_in[24];

    float *pg_src, *pg_pos, *pg_q, *pg_val, *pg_off, *pg_aw, *pg_attn, *pg_tmp, *pg_h;
    cudaGetSymbolAddress((void**)&pg_src,  g_src);
    cudaGetSymbolAddress((void**)&pg_pos,  g_pos);
    cudaGetSymbolAddress((void**)&pg_q,    g_q);
    cudaGetSymbolAddress((void**)&pg_val,  g_val);
    cudaGetSymbolAddress((void**)&pg_off,  g_off);
    cudaGetSymbolAddress((void**)&pg_aw,   g_aw);
    cudaGetSymbolAddress((void**)&pg_attn, g_attn);
    cudaGetSymbolAddress((void**)&pg_tmp,  g_tmp);
    cudaGetSymbolAddress((void**)&pg_h,    g_h);

    const long long totElem = (long long)MROWS * DMODEL;
    const int ew_grid = (int)((totElem + 255) / 256);

    flatten_kernel<<<ew_grid, 256>>>(s0, s1, s2, s3, p0, p1, p2, p3, lvl_emb);

    const dim3 gemm_blk(256);
    const int mblk = (MROWS + 127) / 128;
    const dim3 grid256(mblk, DMODEL / 128);   // N=256 -> 2
    const dim3 grid128(mblk, 1);              // N=128
    const dim3 grid1024(mblk, DFFN / 128);    // N=1024 -> 8
    const int ln_grid = (MROWS * 32 + 255) / 256;
    const int deform_grid = (MROWS * NHEADS * 32 + 255) / 256;

    for (int i = 0; i < NLAYERS_C; i++) {
        const float* so_wi = so_w + (size_t)i * DMODEL * 256;
        const float* so_bi = so_b + (size_t)i * 256;
        const float* aw_wi = aw_w + (size_t)i * DMODEL * 128;
        const float* aw_bi = aw_b + (size_t)i * 128;
        const float* vp_wi = vp_w + (size_t)i * DMODEL * DMODEL;
        const float* vp_bi = vp_b + (size_t)i * DMODEL;
        const float* op_wi = op_w + (size_t)i * DMODEL * DMODEL;
        const float* op_bi = op_b + (size_t)i * DMODEL;
        const float* f1_wi = f1_w + (size_t)i * DMODEL * DFFN;
        const float* f1_bi = f1_b + (size_t)i * DFFN;
        const float* f2_wi = f2_w + (size_t)i * DFFN * DMODEL;
        const float* f2_bi = f2_b + (size_t)i * DMODEL;

        // value = src @ vp_w + vp_b
        gemm128_kernel<false><<<grid256, gemm_blk>>>(pg_src, vp_wi, vp_bi, pg_val,
                                                     MROWS, DMODEL, DMODEL);
        // q = src + pos
        add_q_kernel<<<ew_grid, 256>>>();
        // offsets = q @ so_w + so_b
        gemm128_kernel<false><<<grid256, gemm_blk>>>(pg_q, so_wi, so_bi, pg_off,
                                                     MROWS, DMODEL, 256);
        // aw logits = q @ aw_w + aw_b
        gemm128_kernel<false><<<grid128, gemm_blk>>>(pg_q, aw_wi, aw_bi, pg_aw,
                                                     MROWS, DMODEL, 128);
        // deformable sampling
        deform_kernel<<<deform_grid, 256>>>(pg_val, pg_off, pg_aw, pg_attn);
        // output proj
        gemm128_kernel<false><<<grid256, gemm_blk>>>(pg_attn, op_wi, op_bi, pg_tmp,
                                                     MROWS, DMODEL, DMODEL);
        // src = LN(src + attn_proj)
        add_ln_kernel<<<ln_grid, 256>>>(pg_src, pg_tmp,
                                        n1_w + (size_t)i * DMODEL, n1_b + (size_t)i * DMODEL,
                                        pg_src);
        // h = relu(src @ f1_w + f1_b)
        gemm128_kernel<true><<<grid1024, gemm_blk>>>(pg_src, f1_wi, f1_bi, pg_h,
                                                     MROWS, DMODEL, DFFN);
        // tmp = h @ f2_w + f2_b
        gemm128_kernel<false><<<grid256, gemm_blk>>>(pg_h, f2_wi, f2_bi, pg_tmp,
                                                     MROWS, DFFN, DMODEL);
        // src = LN(src + ffn)
        add_ln_kernel<<<ln_grid, 256>>>(pg_src, pg_tmp,
                                        n2_w + (size_t)i * DMODEL, n2_b + (size_t)i * DMODEL,
                                        pg_src);
    }

    write_out_kernel<<<(out_size + 255) / 256, 256>>>((float*)d_out, out_size);
}

// round 5
// speedup vs baseline: 1.8173x; 1.4961x over previous
#include <cuda_runtime.h>
#include <cuda_bf16.h>
#include <cstdint>
#include <math.h>

// ---------------- problem constants ----------------
#define L_TOT   13294          // 10000 + 2500 + 625 + 169
#define BATCH   4
#define MROWS   (BATCH * L_TOT)   // 53176
#define DMODEL  256
#define DFFN    1024
#define NLAYERS_C 6
#define NHEADS  8

// weight-pair layout offsets (elements) within one layer block
#define OFF_VP  0
#define OFF_SO  65536
#define OFF_AW  131072
#define OFF_OP  163840
#define OFF_F1  229376
#define OFF_F2  491520
#define LW_STRIDE 753664

// ---------------- device scratch (static, allowed) ----------------
__device__ __align__(16) float g_src [MROWS * DMODEL];
__device__ __align__(16) float g_pos [MROWS * DMODEL];
__device__ __align__(16) float g_val [MROWS * DMODEL];
__device__ __align__(16) float g_off [MROWS * DMODEL];
__device__ __align__(16) float g_aw  [MROWS * 128];
__device__ __align__(16) float g_tmp [MROWS * DMODEL];

__device__ __align__(16) __nv_bfloat16 g_src_hi [MROWS * DMODEL];
__device__ __align__(16) __nv_bfloat16 g_src_lo [MROWS * DMODEL];
__device__ __align__(16) __nv_bfloat16 g_q_hi   [MROWS * DMODEL];
__device__ __align__(16) __nv_bfloat16 g_q_lo   [MROWS * DMODEL];
__device__ __align__(16) __nv_bfloat16 g_attn_hi[MROWS * DMODEL];
__device__ __align__(16) __nv_bfloat16 g_attn_lo[MROWS * DMODEL];
__device__ __align__(16) __nv_bfloat16 g_h_hi   [(size_t)MROWS * DFFN];
__device__ __align__(16) __nv_bfloat16 g_h_lo   [(size_t)MROWS * DFFN];
__device__ __align__(16) __nv_bfloat16 g_w_hi   [NLAYERS_C * LW_STRIDE];
__device__ __align__(16) __nv_bfloat16 g_w_lo   [NLAYERS_C * LW_STRIDE];

// ---------------- helpers ----------------
__device__ __forceinline__ uint32_t smem_u32(const void* p) {
    uint32_t a;
    asm("{ .reg .u64 t; cvta.to.shared.u64 t, %1; cvt.u32.u64 %0, t; }" : "=r"(a) : "l"(p));
    return a;
}

__device__ __forceinline__ void split_bf16(float x, __nv_bfloat16& h, __nv_bfloat16& l) {
    h = __float2bfloat16(x);
    l = __float2bfloat16(x - __bfloat162float(h));
}

#define LDMX4(r, addr) \
    asm volatile("ldmatrix.sync.aligned.m8n8.x4.shared.b16 {%0,%1,%2,%3}, [%4];" \
        : "=r"((r)[0]), "=r"((r)[1]), "=r"((r)[2]), "=r"((r)[3]) : "r"(addr))

__device__ __forceinline__ void mma16816(float* c, const uint32_t* a, const uint32_t* b) {
    asm volatile(
        "mma.sync.aligned.m16n8k16.row.col.f32.bf16.bf16.f32 "
        "{%0,%1,%2,%3}, {%4,%5,%6,%7}, {%8,%9}, {%0,%1,%2,%3};\n"
        : "+f"(c[0]), "+f"(c[1]), "+f"(c[2]), "+f"(c[3])
        : "r"(a[0]), "r"(a[1]), "r"(a[2]), "r"(a[3]), "r"(b[0]), "r"(b[1]));
}

// ---------------- weight prep: W[K,N] fp32 -> Wt_hi/lo [N,K] bf16 ----------------
__global__ void wprep_kernel(const float* __restrict__ W,
                             __nv_bfloat16* __restrict__ oh, __nv_bfloat16* __restrict__ ol,
                             int K, int N)
{
    int idx = blockIdx.x * blockDim.x + threadIdx.x;
    if (idx >= K * N) return;
    int n = idx / K, k = idx - n * K;
    float x = __ldg(W + (size_t)k * N + n);
    __nv_bfloat16 h, l;
    split_bf16(x, h, l);
    oh[idx] = h;
    ol[idx] = l;
}

// ---------------- flatten: (B,D,H,W) -> (B,L,D), pos += level_embed; emit src pair --
__global__ void flatten_kernel(const float* __restrict__ s0, const float* __restrict__ s1,
                               const float* __restrict__ s2, const float* __restrict__ s3,
                               const float* __restrict__ p0, const float* __restrict__ p1,
                               const float* __restrict__ p2, const float* __restrict__ p3,
                               const float* __restrict__ lvl_emb)
{
    long long idx = (long long)blockIdx.x * blockDim.x + threadIdx.x;
    const long long tot = (long long)MROWS * DMODEL;
    if (idx >= tot) return;
    int d = (int)(idx & 255);
    int m = (int)(idx >> 8);
    int b = m / L_TOT;
    int n = m - b * L_TOT;
    int lvl, hw, HW;
    const float *sp, *pp;
    if (n < 10000)      { lvl = 0; hw = n;         HW = 10000; sp = s0; pp = p0; }
    else if (n < 12500) { lvl = 1; hw = n - 10000; HW = 2500;  sp = s1; pp = p1; }
    else if (n < 13125) { lvl = 2; hw = n - 12500; HW = 625;   sp = s2; pp = p2; }
    else                { lvl = 3; hw = n - 13125; HW = 169;   sp = s3; pp = p3; }
    size_t sidx = ((size_t)b * DMODEL + d) * HW + hw;
    float sv = __ldg(sp + sidx);
    g_src[idx] = sv;
    g_pos[idx] = __ldg(pp + sidx) + __ldg(lvl_emb + lvl * DMODEL + d);
    __nv_bfloat16 h, l;
    split_bf16(sv, h, l);
    g_src_hi[idx] = h;
    g_src_lo[idx] = l;
}

// ---------------- q = src + pos (bf16 pair only) ----------------
__global__ void add_q_kernel()
{
    long long idx = (long long)blockIdx.x * blockDim.x + threadIdx.x;
    const long long tot = (long long)MROWS * DMODEL;
    if (idx >= tot) return;
    float q = g_src[idx] + g_pos[idx];
    __nv_bfloat16 h, l;
    split_bf16(q, h, l);
    g_q_hi[idx] = h;
    g_q_lo[idx] = l;
}

// ---------------- HMMA split-bf16 GEMM ----------------
// C[M,N] = A[M,K] @ W[K,N] + bias.  A as bf16 hi/lo [M,K]; W as bf16 hi/lo [N,K].
// C ~= Ah*Bh + Ah*Bl + Al*Bh (fp32 accum).  CTA tile 128x64, BK=32, 8 warps (4m x 2n).
// OUTMODE 0: fp32 out (opt RELU); OUTMODE 1: bf16 hi/lo out (opt RELU).
template<bool RELU, int OUTMODE>
__global__ __launch_bounds__(256)
void mma_gemm(const __nv_bfloat16* __restrict__ Ah, const __nv_bfloat16* __restrict__ Al,
              const __nv_bfloat16* __restrict__ Bh, const __nv_bfloat16* __restrict__ Bl,
              const float* __restrict__ bias,
              float* __restrict__ Cf,
              __nv_bfloat16* __restrict__ Chi, __nv_bfloat16* __restrict__ Clo,
              int Mr, int K, int N)
{
    // 80-byte row stride (40 bf16): conflict-free ldmatrix, optimal STS phases
    __shared__ __nv_bfloat16 As[2][128][40];
    __shared__ __nv_bfloat16 Bs[2][64][40];

    const int tid  = threadIdx.x;
    const int lane = tid & 31;
    const int warp = tid >> 5;
    const int wm   = warp & 3;          // 0..3 (m direction, 32 rows each)
    const int wn   = warp >> 2;         // 0..1 (n direction, 32 cols each)
    const int row0 = blockIdx.x * 128;
    const int col0 = blockIdx.y * 64;

    float acc[2][4][4];
    #pragma unroll
    for (int i = 0; i < 2; i++)
        #pragma unroll
        for (int j = 0; j < 4; j++)
            #pragma unroll
            for (int k = 0; k < 4; k++) acc[i][j][k] = 0.f;

    const int nch = K >> 5;

    for (int ch = 0; ch < nch; ch++) {
        const int kb = ch << 5;
        // A tiles: 128 rows x 32 cols (hi+lo): 512 uint4 each -> 2 per thread
        #pragma unroll
        for (int r = 0; r < 2; r++) {
            int idx = r * 256 + tid;
            int ar = idx >> 2, o = (idx & 3) << 3;
            uint4 vh = make_uint4(0, 0, 0, 0), vl = make_uint4(0, 0, 0, 0);
            if (row0 + ar < Mr) {
                size_t g = (size_t)(row0 + ar) * K + kb + o;
                vh = *reinterpret_cast<const uint4*>(Ah + g);
                vl = *reinterpret_cast<const uint4*>(Al + g);
            }
            *reinterpret_cast<uint4*>(&As[0][ar][o]) = vh;
            *reinterpret_cast<uint4*>(&As[1][ar][o]) = vl;
        }
        // B tiles: 64 rows x 32 cols: 256 uint4 -> 1 per thread
        {
            int br = tid >> 2, o = (tid & 3) << 3;
            size_t g = (size_t)(col0 + br) * K + kb + o;
            *reinterpret_cast<uint4*>(&Bs[0][br][o]) = *reinterpret_cast<const uint4*>(Bh + g);
            *reinterpret_cast<uint4*>(&Bs[1][br][o]) = *reinterpret_cast<const uint4*>(Bl + g);
        }
        __syncthreads();

        #pragma unroll
        for (int ks = 0; ks < 2; ks++) {
            const int k0 = ks << 4;
            // A fragments (2 m16 tiles, hi + lo)
            uint32_t afh[2][4], afl[2][4];
            #pragma unroll
            for (int mt = 0; mt < 2; mt++) {
                const int arow = wm * 32 + mt * 16 + (lane & 15);
                const int acol = k0 + ((lane >> 4) << 3);
                LDMX4(afh[mt], smem_u32(&As[0][arow][acol]));
                LDMX4(afl[mt], smem_u32(&As[1][arow][acol]));
            }
            // B fragments (4 n8 tiles, hi + lo): one x4 covers two n8 tiles
            uint32_t bfh[4][2], bfl[4][2];
            #pragma unroll
            for (int np = 0; np < 2; np++) {
                const int tr = wn * 32 + np * 16 + ((lane >> 4) << 3) + (lane & 7);
                const int tc = k0 + (((lane >> 3) & 1) << 3);
                uint32_t t[4];
                LDMX4(t, smem_u32(&Bs[0][tr][tc]));
                bfh[np * 2][0] = t[0]; bfh[np * 2][1] = t[1];
                bfh[np * 2 + 1][0] = t[2]; bfh[np * 2 + 1][1] = t[3];
                LDMX4(t, smem_u32(&Bs[1][tr][tc]));
                bfl[np * 2][0] = t[0]; bfl[np * 2][1] = t[1];
                bfl[np * 2 + 1][0] = t[2]; bfl[np * 2 + 1][1] = t[3];
            }
            // 3-term split mma
            #pragma unroll
            for (int mt = 0; mt < 2; mt++)
                #pragma unroll
                for (int nt = 0; nt < 4; nt++) {
                    mma16816(acc[mt][nt], afh[mt], bfh[nt]);
                    mma16816(acc[mt][nt], afh[mt], bfl[nt]);
                    mma16816(acc[mt][nt], afl[mt], bfh[nt]);
                }
        }
        __syncthreads();
    }

    // epilogue
    const int g  = lane >> 2;
    const int tg = lane & 3;
    #pragma unroll
    for (int mt = 0; mt < 2; mt++) {
        #pragma unroll
        for (int nt = 0; nt < 4; nt++) {
            const int col = col0 + wn * 32 + nt * 8 + tg * 2;
            const float b0 = __ldg(bias + col);
            const float b1 = __ldg(bias + col + 1);
            #pragma unroll
            for (int half = 0; half < 2; half++) {
                const int row = row0 + wm * 32 + mt * 16 + g + half * 8;
                if (row < Mr) {
                    float v0 = acc[mt][nt][half * 2 + 0] + b0;
                    float v1 = acc[mt][nt][half * 2 + 1] + b1;
                    if (RELU) { v0 = fmaxf(v0, 0.f); v1 = fmaxf(v1, 0.f); }
                    if (OUTMODE == 0) {
                        *reinterpret_cast<float2*>(Cf + (size_t)row * N + col) = make_float2(v0, v1);
                    } else {
                        __nv_bfloat16 h0, l0, h1, l1;
                        split_bf16(v0, h0, l0);
                        split_bf16(v1, h1, l1);
                        size_t co = (size_t)row * N + col;
                        *reinterpret_cast<__nv_bfloat162*>(Chi + co) = __halves2bfloat162(h0, h1);
                        *reinterpret_cast<__nv_bfloat162*>(Clo + co) = __halves2bfloat162(l0, l1);
                    }
                }
            }
        }
    }
}

// ---------------- deformable attention sampling (one warp per (b,q,head)) -----------
__global__ void deform_kernel(const float* __restrict__ value,
                              const float* __restrict__ off,
                              const float* __restrict__ aw,
                              __nv_bfloat16* __restrict__ out_hi,
                              __nv_bfloat16* __restrict__ out_lo)
{
    int gw = (int)((blockIdx.x * blockDim.x + threadIdx.x) >> 5);
    if (gw >= MROWS * NHEADS) return;
    int lane = threadIdx.x & 31;
    int h = gw & 7;
    int m = gw >> 3;
    int b = m / L_TOT;
    int q = m - b * L_TOT;

    float ref_x, ref_y;
    {
        int idx, Wl, Hl;
        if (q < 10000)      { idx = q;         Wl = 100; Hl = 100; }
        else if (q < 12500) { idx = q - 10000; Wl = 50;  Hl = 50;  }
        else if (q < 13125) { idx = q - 12500; Wl = 25;  Hl = 25;  }
        else                { idx = q - 13125; Wl = 13;  Hl = 13;  }
        int yy = idx / Wl, xx = idx - yy * Wl;
        ref_x = (xx + 0.5f) / (float)Wl;
        ref_y = (yy + 0.5f) / (float)Hl;
    }

    const float* awp = aw + (size_t)m * 128 + h * 16;
    float e[16];
    float mx = -1e30f;
    #pragma unroll
    for (int i = 0; i < 16; i++) { e[i] = __ldg(awp + i); mx = fmaxf(mx, e[i]); }
    float ssum = 0.f;
    #pragma unroll
    for (int i = 0; i < 16; i++) { e[i] = __expf(e[i] - mx); ssum += e[i]; }
    float inv = 1.f / ssum;

    const float* offp  = off + (size_t)m * 256 + h * 32;
    const float* vbase = value + (size_t)b * L_TOT * 256 + h * 32 + lane;

    const int Ws[4]     = {100, 50, 25, 13};
    const int Hs[4]     = {100, 50, 25, 13};
    const int starts[4] = {0, 10000, 12500, 13125};

    float acc = 0.f;
    #pragma unroll
    for (int l = 0; l < 4; l++) {
        const int   Wl = Ws[l], Hl = Hs[l], st = starts[l];
        const float fW = (float)Wl, fH = (float)Hl;
        #pragma unroll
        for (int p = 0; p < 4; p++) {
            float ox = __ldg(offp + l * 8 + p * 2);
            float oy = __ldg(offp + l * 8 + p * 2 + 1);
            float px = ref_x * fW + ox - 0.5f;
            float py = ref_y * fH + oy - 0.5f;
            float x0f = floorf(px), y0f = floorf(py);
            float wx1 = px - x0f, wy1 = py - y0f;
            int x0 = (int)x0f, y0 = (int)y0f;
            float wgt = e[l * 4 + p] * inv;
            #pragma unroll
            for (int t = 0; t < 4; t++) {
                int xi = x0 + (t & 1);
                int yi = y0 + (t >> 1);
                float w = ((t & 1) ? wx1 : 1.f - wx1) * ((t >> 1) ? wy1 : 1.f - wy1);
                if (xi >= 0 && xi < Wl && yi >= 0 && yi < Hl && w != 0.f) {
                    acc = fmaf(wgt * w,
                               __ldg(vbase + (size_t)(st + yi * Wl + xi) * 256),
                               acc);
                }
            }
        }
    }
    size_t oidx = (size_t)m * 256 + h * 32 + lane;
    __nv_bfloat16 hh, ll;
    split_bf16(acc, hh, ll);
    out_hi[oidx] = hh;
    out_lo[oidx] = ll;
}

// ---------------- fused residual add + LayerNorm (one warp per row), emits pair -----
__global__ void add_ln_kernel(const float* __restrict__ X, const float* __restrict__ R,
                              const float* __restrict__ w, const float* __restrict__ b,
                              float* __restrict__ out,
                              __nv_bfloat16* __restrict__ out_hi,
                              __nv_bfloat16* __restrict__ out_lo)
{
    int row = (int)((blockIdx.x * blockDim.x + threadIdx.x) >> 5);
    if (row >= MROWS) return;
    int lane = threadIdx.x & 31;
    const float* x = X + (size_t)row * DMODEL;
    const float* r = R + (size_t)row * DMODEL;
    float v[8];
    float s = 0.f;
    #pragma unroll
    for (int j = 0; j < 8; j++) {
        int c = lane + j * 32;
        v[j] = x[c] + r[c];
        s += v[j];
    }
    #pragma unroll
    for (int o = 16; o > 0; o >>= 1) s += __shfl_xor_sync(0xFFFFFFFFu, s, o);
    float mean = s * (1.f / 256.f);
    float qv = 0.f;
    #pragma unroll
    for (int j = 0; j < 8; j++) { float d = v[j] - mean; qv += d * d; }
    #pragma unroll
    for (int o = 16; o > 0; o >>= 1) qv += __shfl_xor_sync(0xFFFFFFFFu, qv, o);
    float invs = rsqrtf(qv * (1.f / 256.f) + 1e-5f);
    #pragma unroll
    for (int j = 0; j < 8; j++) {
        int c = lane + j * 32;
        float o = (v[j] - mean) * invs * __ldg(w + c) + __ldg(b + c);
        size_t oi = (size_t)row * DMODEL + c;
        out[oi] = o;
        __nv_bfloat16 hh, ll;
        split_bf16(o, hh, ll);
        out_hi[oi] = hh;
        out_lo[oi] = ll;
    }
}

// ---------------- output write: src then level_start_index (as floats) -------------
__global__ void write_out_kernel(float* __restrict__ out, int n)
{
    long long i = (long long)blockIdx.x * blockDim.x + threadIdx.x;
    if (i >= n) return;
    const long long tot = (long long)MROWS * DMODEL;
    if (i < tot) {
        out[i] = g_src[i];
    } else {
        int k = (int)(i - tot);
        float st;
        switch (k) {
            case 0: st = 0.f;      break;
            case 1: st = 10000.f;  break;
            case 2: st = 12500.f;  break;
            case 3: st = 13125.f;  break;
            default: st = 0.f;     break;
        }
        out[i] = st;
    }
}

// ---------------- host launch ----------------
extern "C" void kernel_launch(void* const* d_in, const int* in_sizes, int n_in,
                              void* d_out, int out_size)
{
    // setup_inputs() dict order is INTERLEAVED: src0, pos0, src1, pos1, ...
    const float* s0 = (const float*)d_in[0];
    const float* p0 = (const float*)d_in[1];
    const float* s1 = (const float*)d_in[2];
    const float* p1 = (const float*)d_in[3];
    const float* s2 = (const float*)d_in[4];
    const float* p2 = (const float*)d_in[5];
    const float* s3 = (const float*)d_in[6];
    const float* p3 = (const float*)d_in[7];
    const float* lvl_emb = (const float*)d_in[8];
    const float* so_w = (const float*)d_in[9];
    const float* so_b = (const float*)d_in[10];
    const float* aw_w = (const float*)d_in[11];
    const float* aw_b = (const float*)d_in[12];
    const float* vp_w = (const float*)d_in[13];
    const float* vp_b = (const float*)d_in[14];
    const float* op_w = (const float*)d_in[15];
    const float* op_b = (const float*)d_in[16];
    const float* n1_w = (const float*)d_in[17];
    const float* n1_b = (const float*)d_in[18];
    const float* f1_w = (const float*)d_in[19];
    const float* f1_b = (const float*)d_in[20];
    const float* f2_w = (const float*)d_in[21];
    const float* f2_b = (const float*)d_in[22];
    const float* n2_w = (const float*)d_in[23];
    const float* n2_b = (const float*)d_in[24];

    float *pg_src, *pg_pos, *pg_val, *pg_off, *pg_aw, *pg_tmp;
    __nv_bfloat16 *pg_src_hi, *pg_src_lo, *pg_q_hi, *pg_q_lo;
    __nv_bfloat16 *pg_attn_hi, *pg_attn_lo, *pg_h_hi, *pg_h_lo, *pg_w_hi, *pg_w_lo;
    cudaGetSymbolAddress((void**)&pg_src,  g_src);
    cudaGetSymbolAddress((void**)&pg_pos,  g_pos);
    cudaGetSymbolAddress((void**)&pg_val,  g_val);
    cudaGetSymbolAddress((void**)&pg_off,  g_off);
    cudaGetSymbolAddress((void**)&pg_aw,   g_aw);
    cudaGetSymbolAddress((void**)&pg_tmp,  g_tmp);
    cudaGetSymbolAddress((void**)&pg_src_hi, g_src_hi);
    cudaGetSymbolAddress((void**)&pg_src_lo, g_src_lo);
    cudaGetSymbolAddress((void**)&pg_q_hi,   g_q_hi);
    cudaGetSymbolAddress((void**)&pg_q_lo,   g_q_lo);
    cudaGetSymbolAddress((void**)&pg_attn_hi, g_attn_hi);
    cudaGetSymbolAddress((void**)&pg_attn_lo, g_attn_lo);
    cudaGetSymbolAddress((void**)&pg_h_hi,   g_h_hi);
    cudaGetSymbolAddress((void**)&pg_h_lo,   g_h_lo);
    cudaGetSymbolAddress((void**)&pg_w_hi,   g_w_hi);
    cudaGetSymbolAddress((void**)&pg_w_lo,   g_w_lo);

    const long long totElem = (long long)MROWS * DMODEL;
    const int ew_grid = (int)((totElem + 255) / 256);

    // ---- weight prep (transpose + bf16 split), all layers ----
    for (int i = 0; i < NLAYERS_C; i++) {
        size_t wb = (size_t)i * LW_STRIDE;
        wprep_kernel<<<(65536 + 255) / 256, 256>>>(vp_w + (size_t)i * 65536, pg_w_hi + wb + OFF_VP, pg_w_lo + wb + OFF_VP, 256, 256);
        wprep_kernel<<<(65536 + 255) / 256, 256>>>(so_w + (size_t)i * 65536, pg_w_hi + wb + OFF_SO, pg_w_lo + wb + OFF_SO, 256, 256);
        wprep_kernel<<<(32768 + 255) / 256, 256>>>(aw_w + (size_t)i * 32768, pg_w_hi + wb + OFF_AW, pg_w_lo + wb + OFF_AW, 256, 128);
        wprep_kernel<<<(65536 + 255) / 256, 256>>>(op_w + (size_t)i * 65536, pg_w_hi + wb + OFF_OP, pg_w_lo + wb + OFF_OP, 256, 256);
        wprep_kernel<<<(262144 + 255) / 256, 256>>>(f1_w + (size_t)i * 262144, pg_w_hi + wb + OFF_F1, pg_w_lo + wb + OFF_F1, 256, 1024);
        wprep_kernel<<<(262144 + 255) / 256, 256>>>(f2_w + (size_t)i * 262144, pg_w_hi + wb + OFF_F2, pg_w_lo + wb + OFF_F2, 1024, 256);
    }

    flatten_kernel<<<ew_grid, 256>>>(s0, s1, s2, s3, p0, p1, p2, p3, lvl_emb);

    const int mblk = (MROWS + 127) / 128;   // 416
    const dim3 blk(256);
    const int ln_grid = (MROWS * 32 + 255) / 256;
    const int deform_grid = (MROWS * NHEADS * 32 + 255) / 256;

    for (int i = 0; i < NLAYERS_C; i++) {
        size_t wb = (size_t)i * LW_STRIDE;
        const __nv_bfloat16* vp_h = pg_w_hi + wb + OFF_VP; const __nv_bfloat16* vp_l = pg_w_lo + wb + OFF_VP;
        const __nv_bfloat16* so_h = pg_w_hi + wb + OFF_SO; const __nv_bfloat16* so_l = pg_w_lo + wb + OFF_SO;
        const __nv_bfloat16* aw_h = pg_w_hi + wb + OFF_AW; const __nv_bfloat16* aw_l = pg_w_lo + wb + OFF_AW;
        const __nv_bfloat16* op_h = pg_w_hi + wb + OFF_OP; const __nv_bfloat16* op_l = pg_w_lo + wb + OFF_OP;
        const __nv_bfloat16* f1_h = pg_w_hi + wb + OFF_F1; const __nv_bfloat16* f1_l = pg_w_lo + wb + OFF_F1;
        const __nv_bfloat16* f2_h = pg_w_hi + wb + OFF_F2; const __nv_bfloat16* f2_l = pg_w_lo + wb + OFF_F2;

        // value = src @ vp_w + vp_b  (fp32 out)
        mma_gemm<false, 0><<<dim3(mblk, 4), blk>>>(
            pg_src_hi, pg_src_lo, vp_h, vp_l, vp_b + (size_t)i * 256,
            pg_val, nullptr, nullptr, MROWS, 256, 256);
        // q = src + pos (pair)
        add_q_kernel<<<ew_grid, 256>>>();
        // offsets = q @ so_w + so_b
        mma_gemm<false, 0><<<dim3(mblk, 4), blk>>>(
            pg_q_hi, pg_q_lo, so_h, so_l, so_b + (size_t)i * 256,
            pg_off, nullptr, nullptr, MROWS, 256, 256);
        // aw logits = q @ aw_w + aw_b
        mma_gemm<false, 0><<<dim3(mblk, 2), blk>>>(
            pg_q_hi, pg_q_lo, aw_h, aw_l, aw_b + (size_t)i * 128,
            pg_aw, nullptr, nullptr, MROWS, 256, 128);
        // deformable sampling -> attn pair
        deform_kernel<<<deform_grid, 256>>>(pg_val, pg_off, pg_aw, pg_attn_hi, pg_attn_lo);
        // output proj
        mma_gemm<false, 0><<<dim3(mblk, 4), blk>>>(
            pg_attn_hi, pg_attn_lo, op_h, op_l, op_b + (size_t)i * 256,
            pg_tmp, nullptr, nullptr, MROWS, 256, 256);
        // src = LN(src + attn_proj)
        add_ln_kernel<<<ln_grid, 256>>>(pg_src, pg_tmp,
                                        n1_w + (size_t)i * DMODEL, n1_b + (size_t)i * DMODEL,
                                        pg_src, pg_src_hi, pg_src_lo);
        // h = relu(src @ f1_w + f1_b)  (bf16 pair out)
        mma_gemm<true, 1><<<dim3(mblk, 16), blk>>>(
            pg_src_hi, pg_src_lo, f1_h, f1_l, f1_b + (size_t)i * DFFN,
            nullptr, pg_h_hi, pg_h_lo, MROWS, 256, DFFN);
        // tmp = h @ f2_w + f2_b
        mma_gemm<false, 0><<<dim3(mblk, 4), blk>>>(
            pg_h_hi, pg_h_lo, f2_h, f2_l, f2_b + (size_t)i * 256,
            pg_tmp, nullptr, nullptr, MROWS, 1024, 256);
        // src = LN(src + ffn)
        add_ln_kernel<<<ln_grid, 256>>>(pg_src, pg_tmp,
                                        n2_w + (size_t)i * DMODEL, n2_b + (size_t)i * DMODEL,
                                        pg_src, pg_src_hi, pg_src_lo);
    }

    write_out_kernel<<<(out_size + 255) / 256, 256>>>((float*)d_out, out_size);
}

// round 6
// speedup vs baseline: 2.0209x; 1.1120x over previous
#include <cuda_runtime.h>
#include <cuda_bf16.h>
#include <cstdint>
#include <math.h>

// ---------------- problem constants ----------------
#define L_TOT   13294          // 10000 + 2500 + 625 + 169
#define BATCH   4
#define MROWS   (BATCH * L_TOT)   // 53176
#define DMODEL  256
#define DFFN    1024
#define NLAYERS_C 6
#define NHEADS  8

// weight-pair layout offsets (elements) within one layer block
#define OFF_VP    0
#define OFF_SOAW  65536          // combined so(256) + aw(128) rows => [384,256]
#define OFF_OP    163840
#define OFF_F1    229376
#define OFF_F2    491520
#define LW_STRIDE 753664

// ---------------- device scratch (static, allowed) ----------------
__device__ __align__(16) float g_src  [MROWS * DMODEL];
__device__ __align__(16) float g_pos  [MROWS * DMODEL];
__device__ __align__(16) float g_val  [MROWS * DMODEL];
__device__ __align__(16) float g_offaw[MROWS * 384];
__device__ __align__(16) float g_tmp  [MROWS * DMODEL];

__device__ __align__(16) __nv_bfloat16 g_src_hi [MROWS * DMODEL];
__device__ __align__(16) __nv_bfloat16 g_src_lo [MROWS * DMODEL];
__device__ __align__(16) __nv_bfloat16 g_q_hi   [MROWS * DMODEL];
__device__ __align__(16) __nv_bfloat16 g_q_lo   [MROWS * DMODEL];
__device__ __align__(16) __nv_bfloat16 g_attn_hi[MROWS * DMODEL];
__device__ __align__(16) __nv_bfloat16 g_attn_lo[MROWS * DMODEL];
__device__ __align__(16) __nv_bfloat16 g_h_hi   [(size_t)MROWS * DFFN];
__device__ __align__(16) __nv_bfloat16 g_h_lo   [(size_t)MROWS * DFFN];
__device__ __align__(16) __nv_bfloat16 g_w_hi   [NLAYERS_C * LW_STRIDE];
__device__ __align__(16) __nv_bfloat16 g_w_lo   [NLAYERS_C * LW_STRIDE];

// ---------------- helpers ----------------
__device__ __forceinline__ uint32_t smem_u32(const void* p) {
    uint32_t a;
    asm("{ .reg .u64 t; cvta.to.shared.u64 t, %1; cvt.u32.u64 %0, t; }" : "=r"(a) : "l"(p));
    return a;
}

__device__ __forceinline__ void split_bf16(float x, __nv_bfloat16& h, __nv_bfloat16& l) {
    h = __float2bfloat16(x);
    l = __float2bfloat16(x - __bfloat162float(h));
}

#define LDMX4(r, addr) \
    asm volatile("ldmatrix.sync.aligned.m8n8.x4.shared.b16 {%0,%1,%2,%3}, [%4];" \
        : "=r"((r)[0]), "=r"((r)[1]), "=r"((r)[2]), "=r"((r)[3]) : "r"(addr))

__device__ __forceinline__ void mma16816(float* c, const uint32_t* a, const uint32_t* b) {
    asm volatile(
        "mma.sync.aligned.m16n8k16.row.col.f32.bf16.bf16.f32 "
        "{%0,%1,%2,%3}, {%4,%5,%6,%7}, {%8,%9}, {%0,%1,%2,%3};\n"
        : "+f"(c[0]), "+f"(c[1]), "+f"(c[2]), "+f"(c[3])
        : "r"(a[0]), "r"(a[1]), "r"(a[2]), "r"(a[3]), "r"(b[0]), "r"(b[1]));
}

#define CP_ASYNC16(dst, src, sz) \
    asm volatile("cp.async.cg.shared.global [%0], [%1], 16, %2;" \
        :: "r"(dst), "l"(src), "r"(sz))
#define CP_COMMIT() asm volatile("cp.async.commit_group;" ::: "memory")
#define CP_WAIT0()  asm volatile("cp.async.wait_group 0;" ::: "memory")

// ---------------- weight prep (all layers in one launch per weight type) -----------
// W fp32 [nlayers, K, N] -> dst hi/lo bf16 [nlayers(dst_stride), N, K]
__global__ void wprep_kernel(const float* __restrict__ W,
                             __nv_bfloat16* __restrict__ oh, __nv_bfloat16* __restrict__ ol,
                             int K, int N, int nlayers, size_t dst_stride)
{
    int idx = blockIdx.x * blockDim.x + threadIdx.x;
    int per = K * N;
    if (idx >= per * nlayers) return;
    int l = idx / per;
    int rem = idx - l * per;
    int n = rem / K, k = rem - n * K;
    float x = __ldg(W + (size_t)l * per + (size_t)k * N + n);
    __nv_bfloat16 h, lo;
    split_bf16(x, h, lo);
    size_t d = (size_t)l * dst_stride + (size_t)n * K + k;
    oh[d] = h;
    ol[d] = lo;
}

// ---------------- flatten: (B,D,H,W) -> (B,L,D); emits src pair + q pair -----------
__global__ void flatten_kernel(const float* __restrict__ s0, const float* __restrict__ s1,
                               const float* __restrict__ s2, const float* __restrict__ s3,
                               const float* __restrict__ p0, const float* __restrict__ p1,
                               const float* __restrict__ p2, const float* __restrict__ p3,
                               const float* __restrict__ lvl_emb)
{
    long long idx = (long long)blockIdx.x * blockDim.x + threadIdx.x;
    const long long tot = (long long)MROWS * DMODEL;
    if (idx >= tot) return;
    int d = (int)(idx & 255);
    int m = (int)(idx >> 8);
    int b = m / L_TOT;
    int n = m - b * L_TOT;
    int lvl, hw, HW;
    const float *sp, *pp;
    if (n < 10000)      { lvl = 0; hw = n;         HW = 10000; sp = s0; pp = p0; }
    else if (n < 12500) { lvl = 1; hw = n - 10000; HW = 2500;  sp = s1; pp = p1; }
    else if (n < 13125) { lvl = 2; hw = n - 12500; HW = 625;   sp = s2; pp = p2; }
    else                { lvl = 3; hw = n - 13125; HW = 169;   sp = s3; pp = p3; }
    size_t sidx = ((size_t)b * DMODEL + d) * HW + hw;
    float sv = __ldg(sp + sidx);
    float pv = __ldg(pp + sidx) + __ldg(lvl_emb + lvl * DMODEL + d);
    g_src[idx] = sv;
    g_pos[idx] = pv;
    __nv_bfloat16 h, l;
    split_bf16(sv, h, l);
    g_src_hi[idx] = h; g_src_lo[idx] = l;
    split_bf16(sv + pv, h, l);
    g_q_hi[idx] = h; g_q_lo[idx] = l;
}

// ---------------- HMMA split-bf16 GEMM, cp.async double-buffered --------------------
// C[M,N] = A[M,K] @ W[K,N] + bias.  A bf16 hi/lo [M,K]; W bf16 hi/lo [N,K].
// CTA 128x64, BK=32, 8 warps (4m x 2n).  bias col<bias_split -> bias[col], else bias2[col-split].
// OUTMODE 0: fp32 out (opt RELU); OUTMODE 1: bf16 hi/lo out (opt RELU).
template<bool RELU, int OUTMODE>
__global__ __launch_bounds__(256)
void mma_gemm(const __nv_bfloat16* __restrict__ Ah, const __nv_bfloat16* __restrict__ Al,
              const __nv_bfloat16* __restrict__ Bh, const __nv_bfloat16* __restrict__ Bl,
              const float* __restrict__ bias, const float* __restrict__ bias2, int bias_split,
              float* __restrict__ Cf,
              __nv_bfloat16* __restrict__ Chi, __nv_bfloat16* __restrict__ Clo,
              int Mr, int K, int N)
{
    extern __shared__ char smem[];
    // per stage: AsH[128][40] AsL[128][40] BsH[64][40] BsL[64][40] (bf16, 80B rows)
    const int ASZ = 128 * 80;          // 10240 B
    const int BSZ = 64 * 80;           // 5120 B
    const int STG = 2 * ASZ + 2 * BSZ; // 30720 B

    const int tid  = threadIdx.x;
    const int lane = tid & 31;
    const int warp = tid >> 5;
    const int wm   = warp & 3;
    const int wn   = warp >> 2;
    const int row0 = blockIdx.x * 128;
    const int col0 = blockIdx.y * 64;

    const uint32_t smem_base = smem_u32(smem);

    // cp.async source/dest indexing
    const int aRow = tid >> 2;            // 0..63 (two rows: aRow, aRow+64)
    const int aOff = (tid & 3) << 3;      // element offset 0,8,16,24
    const int bRow = tid >> 2;            // 0..63
    const int bOff = (tid & 3) << 3;

    float acc[2][4][4];
    #pragma unroll
    for (int i = 0; i < 2; i++)
        #pragma unroll
        for (int j = 0; j < 4; j++)
            #pragma unroll
            for (int k = 0; k < 4; k++) acc[i][j][k] = 0.f;

    const int nch = K >> 5;

    // ---- load chunk macro (as lambda) ----
    auto load_chunk = [&](int ch, int stage) {
        const int kb = ch << 5;
        const uint32_t sb = smem_base + stage * STG;
        // A hi/lo: rows aRow and aRow+64
        #pragma unroll
        for (int r = 0; r < 2; r++) {
            const int ar = aRow + r * 64;
            const int ok = (row0 + ar < Mr) ? 16 : 0;
            const size_t g = (size_t)(row0 + ar) * K + kb + aOff;
            const uint32_t so = sb + ar * 80 + aOff * 2;
            CP_ASYNC16(so,        Ah + g, ok);
            CP_ASYNC16(so + ASZ,  Al + g, ok);
        }
        // B hi/lo
        {
            const size_t g = (size_t)(col0 + bRow) * K + kb + bOff;
            const uint32_t so = sb + 2 * ASZ + bRow * 80 + bOff * 2;
            CP_ASYNC16(so,       Bh + g, 16);
            CP_ASYNC16(so + BSZ, Bl + g, 16);
        }
    };

    load_chunk(0, 0);
    CP_COMMIT();

    for (int ch = 0; ch < nch; ch++) {
        const int buf = ch & 1;
        CP_WAIT0();
        __syncthreads();
        if (ch + 1 < nch) {
            load_chunk(ch + 1, buf ^ 1);
            CP_COMMIT();
        }
        const uint32_t sb = smem_base + buf * STG;

        #pragma unroll
        for (int ks = 0; ks < 2; ks++) {
            const int k0 = ks << 4;
            uint32_t afh[2][4], afl[2][4];
            #pragma unroll
            for (int mt = 0; mt < 2; mt++) {
                const int arow = wm * 32 + mt * 16 + (lane & 15);
                const int acol = k0 + ((lane >> 4) << 3);
                const uint32_t ad = sb + arow * 80 + acol * 2;
                LDMX4(afh[mt], ad);
                LDMX4(afl[mt], ad + ASZ);
            }
            uint32_t bfh[4][2], bfl[4][2];
            #pragma unroll
            for (int np = 0; np < 2; np++) {
                const int tr = wn * 32 + np * 16 + ((lane >> 4) << 3) + (lane & 7);
                const int tc = k0 + (((lane >> 3) & 1) << 3);
                const uint32_t bd = sb + 2 * ASZ + tr * 80 + tc * 2;
                uint32_t t[4];
                LDMX4(t, bd);
                bfh[np * 2][0] = t[0]; bfh[np * 2][1] = t[1];
                bfh[np * 2 + 1][0] = t[2]; bfh[np * 2 + 1][1] = t[3];
                LDMX4(t, bd + BSZ);
                bfl[np * 2][0] = t[0]; bfl[np * 2][1] = t[1];
                bfl[np * 2 + 1][0] = t[2]; bfl[np * 2 + 1][1] = t[3];
            }
            #pragma unroll
            for (int mt = 0; mt < 2; mt++)
                #pragma unroll
                for (int nt = 0; nt < 4; nt++) {
                    mma16816(acc[mt][nt], afh[mt], bfh[nt]);
                    mma16816(acc[mt][nt], afh[mt], bfl[nt]);
                    mma16816(acc[mt][nt], afl[mt], bfh[nt]);
                }
        }
        __syncthreads();
    }

    // epilogue
    const int g  = lane >> 2;
    const int tg = lane & 3;
    #pragma unroll
    for (int mt = 0; mt < 2; mt++) {
        #pragma unroll
        for (int nt = 0; nt < 4; nt++) {
            const int col = col0 + wn * 32 + nt * 8 + tg * 2;
            float b0, b1;
            if (col < bias_split) {
                b0 = __ldg(bias + col);
                b1 = __ldg(bias + col + 1);
            } else {
                b0 = __ldg(bias2 + col - bias_split);
                b1 = __ldg(bias2 + col - bias_split + 1);
            }
            #pragma unroll
            for (int half = 0; half < 2; half++) {
                const int row = row0 + wm * 32 + mt * 16 + g + half * 8;
                if (row < Mr) {
                    float v0 = acc[mt][nt][half * 2 + 0] + b0;
                    float v1 = acc[mt][nt][half * 2 + 1] + b1;
                    if (RELU) { v0 = fmaxf(v0, 0.f); v1 = fmaxf(v1, 0.f); }
                    if (OUTMODE == 0) {
                        *reinterpret_cast<float2*>(Cf + (size_t)row * N + col) = make_float2(v0, v1);
                    } else {
                        __nv_bfloat16 h0, l0, h1, l1;
                        split_bf16(v0, h0, l0);
                        split_bf16(v1, h1, l1);
                        size_t co = (size_t)row * N + col;
                        *reinterpret_cast<__nv_bfloat162*>(Chi + co) = __halves2bfloat162(h0, h1);
                        *reinterpret_cast<__nv_bfloat162*>(Clo + co) = __halves2bfloat162(l0, l1);
                    }
                }
            }
        }
    }
}

// ---------------- deformable attention sampling (one warp per (b,q,head)) -----------
// offaw row layout: [0,256) = offsets (h*32 each), [256,384) = aw logits (h*16 each)
__global__ void deform_kernel(const float* __restrict__ value,
                              const float* __restrict__ offaw,
                              __nv_bfloat16* __restrict__ out_hi,
                              __nv_bfloat16* __restrict__ out_lo)
{
    int gw = (int)((blockIdx.x * blockDim.x + threadIdx.x) >> 5);
    if (gw >= MROWS * NHEADS) return;
    int lane = threadIdx.x & 31;
    int h = gw & 7;
    int m = gw >> 3;
    int b = m / L_TOT;
    int q = m - b * L_TOT;

    float ref_x, ref_y;
    {
        int idx, Wl, Hl;
        if (q < 10000)      { idx = q;         Wl = 100; Hl = 100; }
        else if (q < 12500) { idx = q - 10000; Wl = 50;  Hl = 50;  }
        else if (q < 13125) { idx = q - 12500; Wl = 25;  Hl = 25;  }
        else                { idx = q - 13125; Wl = 13;  Hl = 13;  }
        int yy = idx / Wl, xx = idx - yy * Wl;
        ref_x = (xx + 0.5f) / (float)Wl;
        ref_y = (yy + 0.5f) / (float)Hl;
    }

    const float* awp = offaw + (size_t)m * 384 + 256 + h * 16;
    float e[16];
    float mx = -1e30f;
    #pragma unroll
    for (int i = 0; i < 16; i++) { e[i] = __ldg(awp + i); mx = fmaxf(mx, e[i]); }
    float ssum = 0.f;
    #pragma unroll
    for (int i = 0; i < 16; i++) { e[i] = __expf(e[i] - mx); ssum += e[i]; }
    float inv = 1.f / ssum;

    const float* offp  = offaw + (size_t)m * 384 + h * 32;
    const float* vbase = value + (size_t)b * L_TOT * 256 + h * 32 + lane;

    const int Ws[4]     = {100, 50, 25, 13};
    const int Hs[4]     = {100, 50, 25, 13};
    const int starts[4] = {0, 10000, 12500, 13125};

    float acc = 0.f;
    #pragma unroll
    for (int l = 0; l < 4; l++) {
        const int   Wl = Ws[l], Hl = Hs[l], st = starts[l];
        const float fW = (float)Wl, fH = (float)Hl;
        #pragma unroll
        for (int p = 0; p < 4; p++) {
            float ox = __ldg(offp + l * 8 + p * 2);
            float oy = __ldg(offp + l * 8 + p * 2 + 1);
            float px = ref_x * fW + ox - 0.5f;
            float py = ref_y * fH + oy - 0.5f;
            float x0f = floorf(px), y0f = floorf(py);
            float wx1 = px - x0f, wy1 = py - y0f;
            int x0 = (int)x0f, y0 = (int)y0f;
            float wgt = e[l * 4 + p] * inv;
            #pragma unroll
            for (int t = 0; t < 4; t++) {
                int xi = x0 + (t & 1);
                int yi = y0 + (t >> 1);
                float w = ((t & 1) ? wx1 : 1.f - wx1) * ((t >> 1) ? wy1 : 1.f - wy1);
                if (xi >= 0 && xi < Wl && yi >= 0 && yi < Hl && w != 0.f) {
                    acc = fmaf(wgt * w,
                               __ldg(vbase + (size_t)(st + yi * Wl + xi) * 256),
                               acc);
                }
            }
        }
    }
    size_t oidx = (size_t)m * 256 + h * 32 + lane;
    __nv_bfloat16 hh, ll;
    split_bf16(acc, hh, ll);
    out_hi[oidx] = hh;
    out_lo[oidx] = ll;
}

// ---------------- fused residual add + LayerNorm (one warp per row) -----------------
// emits fp32 out + bf16 pair; if pos != nullptr also emits q pair = split(out + pos)
__global__ void add_ln_kernel(const float* __restrict__ X, const float* __restrict__ R,
                              const float* __restrict__ w, const float* __restrict__ b,
                              const float* __restrict__ pos,
                              float* __restrict__ out,
                              __nv_bfloat16* __restrict__ out_hi,
                              __nv_bfloat16* __restrict__ out_lo,
                              __nv_bfloat16* __restrict__ q_hi,
                              __nv_bfloat16* __restrict__ q_lo)
{
    int row = (int)((blockIdx.x * blockDim.x + threadIdx.x) >> 5);
    if (row >= MROWS) return;
    int lane = threadIdx.x & 31;
    const float* x = X + (size_t)row * DMODEL;
    const float* r = R + (size_t)row * DMODEL;
    float v[8];
    float s = 0.f;
    #pragma unroll
    for (int j = 0; j < 8; j++) {
        int c = lane + j * 32;
        v[j] = x[c] + r[c];
        s += v[j];
    }
    #pragma unroll
    for (int o = 16; o > 0; o >>= 1) s += __shfl_xor_sync(0xFFFFFFFFu, s, o);
    float mean = s * (1.f / 256.f);
    float qv = 0.f;
    #pragma unroll
    for (int j = 0; j < 8; j++) { float d = v[j] - mean; qv += d * d; }
    #pragma unroll
    for (int o = 16; o > 0; o >>= 1) qv += __shfl_xor_sync(0xFFFFFFFFu, qv, o);
    float invs = rsqrtf(qv * (1.f / 256.f) + 1e-5f);
    #pragma unroll
    for (int j = 0; j < 8; j++) {
        int c = lane + j * 32;
        float o = (v[j] - mean) * invs * __ldg(w + c) + __ldg(b + c);
        size_t oi = (size_t)row * DMODEL + c;
        out[oi] = o;
        __nv_bfloat16 hh, ll;
        split_bf16(o, hh, ll);
        out_hi[oi] = hh;
        out_lo[oi] = ll;
        if (pos != nullptr) {
            split_bf16(o + __ldg(pos + oi), hh, ll);
            q_hi[oi] = hh;
            q_lo[oi] = ll;
        }
    }
}

// ---------------- output write: src then level_start_index (as floats) -------------
__global__ void write_out_kernel(float* __restrict__ out, int n)
{
    long long i = (long long)blockIdx.x * blockDim.x + threadIdx.x;
    if (i >= n) return;
    const long long tot = (long long)MROWS * DMODEL;
    if (i < tot) {
        out[i] = g_src[i];
    } else {
        int k = (int)(i - tot);
        float st;
        switch (k) {
            case 0: st = 0.f;      break;
            case 1: st = 10000.f;  break;
            case 2: st = 12500.f;  break;
            case 3: st = 13125.f;  break;
            default: st = 0.f;     break;
        }
        out[i] = st;
    }
}

// ---------------- host launch ----------------
extern "C" void kernel_launch(void* const* d_in, const int* in_sizes, int n_in,
                              void* d_out, int out_size)
{
    // setup_inputs() dict order is INTERLEAVED: src0, pos0, src1, pos1, ...
    const float* s0 = (const float*)d_in[0];
    const float* p0 = (const float*)d_in[1];
    const float* s1 = (const float*)d_in[2];
    const float* p1 = (const float*)d_in[3];
    const float* s2 = (const float*)d_in[4];
    const float* p2 = (const float*)d_in[5];
    const float* s3 = (const float*)d_in[6];
    const float* p3 = (const float*)d_in[7];
    const float* lvl_emb = (const float*)d_in[8];
    const float* so_w = (const float*)d_in[9];
    const float* so_b = (const float*)d_in[10];
    const float* aw_w = (const float*)d_in[11];
    const float* aw_b = (const float*)d_in[12];
    const float* vp_w = (const float*)d_in[13];
    const float* vp_b = (const float*)d_in[14];
    const float* op_w = (const float*)d_in[15];
    const float* op_b = (const float*)d_in[16];
    const float* n1_w = (const float*)d_in[17];
    const float* n1_b = (const float*)d_in[18];
    const float* f1_w = (const float*)d_in[19];
    const float* f1_b = (const float*)d_in[20];
    const float* f2_w = (const float*)d_in[21];
    const float* f2_b = (const float*)d_in[22];
    const float* n2_w = (const float*)d_in[23];
    const float* n2_b = (const float*)d_in[24];

    float *pg_src, *pg_pos, *pg_val, *pg_offaw, *pg_tmp;
    __nv_bfloat16 *pg_src_hi, *pg_src_lo, *pg_q_hi, *pg_q_lo;
    __nv_bfloat16 *pg_attn_hi, *pg_attn_lo, *pg_h_hi, *pg_h_lo, *pg_w_hi, *pg_w_lo;
    cudaGetSymbolAddress((void**)&pg_src,   g_src);
    cudaGetSymbolAddress((void**)&pg_pos,   g_pos);
    cudaGetSymbolAddress((void**)&pg_val,   g_val);
    cudaGetSymbolAddress((void**)&pg_offaw, g_offaw);
    cudaGetSymbolAddress((void**)&pg_tmp,   g_tmp);
    cudaGetSymbolAddress((void**)&pg_src_hi, g_src_hi);
    cudaGetSymbolAddress((void**)&pg_src_lo, g_src_lo);
    cudaGetSymbolAddress((void**)&pg_q_hi,   g_q_hi);
    cudaGetSymbolAddress((void**)&pg_q_lo,   g_q_lo);
    cudaGetSymbolAddress((void**)&pg_attn_hi, g_attn_hi);
    cudaGetSymbolAddress((void**)&pg_attn_lo, g_attn_lo);
    cudaGetSymbolAddress((void**)&pg_h_hi,   g_h_hi);
    cudaGetSymbolAddress((void**)&pg_h_lo,   g_h_lo);
    cudaGetSymbolAddress((void**)&pg_w_hi,   g_w_hi);
    cudaGetSymbolAddress((void**)&pg_w_lo,   g_w_lo);

    // dynamic smem for GEMM: 2 stages x 30720 B
    const int GEMM_SMEM = 61440;
    cudaFuncSetAttribute(mma_gemm<false, 0>, cudaFuncAttributeMaxDynamicSharedMemorySize, GEMM_SMEM);
    cudaFuncSetAttribute(mma_gemm<true, 1>,  cudaFuncAttributeMaxDynamicSharedMemorySize, GEMM_SMEM);

    const long long totElem = (long long)MROWS * DMODEL;
    const int ew_grid = (int)((totElem + 255) / 256);

    // ---- weight prep: 6 launches, all layers each ----
    wprep_kernel<<<(NLAYERS_C * 65536 + 255) / 256, 256>>>(vp_w, pg_w_hi + OFF_VP, pg_w_lo + OFF_VP, 256, 256, NLAYERS_C, LW_STRIDE);
    wprep_kernel<<<(NLAYERS_C * 65536 + 255) / 256, 256>>>(so_w, pg_w_hi + OFF_SOAW, pg_w_lo + OFF_SOAW, 256, 256, NLAYERS_C, LW_STRIDE);
    wprep_kernel<<<(NLAYERS_C * 32768 + 255) / 256, 256>>>(aw_w, pg_w_hi + OFF_SOAW + 65536, pg_w_lo + OFF_SOAW + 65536, 256, 128, NLAYERS_C, LW_STRIDE);
    wprep_kernel<<<(NLAYERS_C * 65536 + 255) / 256, 256>>>(op_w, pg_w_hi + OFF_OP, pg_w_lo + OFF_OP, 256, 256, NLAYERS_C, LW_STRIDE);
    wprep_kernel<<<(NLAYERS_C * 262144 + 255) / 256, 256>>>(f1_w, pg_w_hi + OFF_F1, pg_w_lo + OFF_F1, 256, 1024, NLAYERS_C, LW_STRIDE);
    wprep_kernel<<<(NLAYERS_C * 262144 + 255) / 256, 256>>>(f2_w, pg_w_hi + OFF_F2, pg_w_lo + OFF_F2, 1024, 256, NLAYERS_C, LW_STRIDE);

    flatten_kernel<<<ew_grid, 256>>>(s0, s1, s2, s3, p0, p1, p2, p3, lvl_emb);

    const int mblk = (MROWS + 127) / 128;   // 416
    const dim3 blk(256);
    const int ln_grid = (MROWS * 32 + 255) / 256;
    const int deform_grid = (MROWS * NHEADS * 32 + 255) / 256;

    for (int i = 0; i < NLAYERS_C; i++) {
        size_t wb = (size_t)i * LW_STRIDE;
        const __nv_bfloat16* vp_h = pg_w_hi + wb + OFF_VP;   const __nv_bfloat16* vp_l = pg_w_lo + wb + OFF_VP;
        const __nv_bfloat16* sa_h = pg_w_hi + wb + OFF_SOAW; const __nv_bfloat16* sa_l = pg_w_lo + wb + OFF_SOAW;
        const __nv_bfloat16* op_h = pg_w_hi + wb + OFF_OP;   const __nv_bfloat16* op_l = pg_w_lo + wb + OFF_OP;
        const __nv_bfloat16* f1_h = pg_w_hi + wb + OFF_F1;   const __nv_bfloat16* f1_l = pg_w_lo + wb + OFF_F1;
        const __nv_bfloat16* f2_h = pg_w_hi + wb + OFF_F2;   const __nv_bfloat16* f2_l = pg_w_lo + wb + OFF_F2;

        // value = src @ vp_w + vp_b  (fp32 out)
        mma_gemm<false, 0><<<dim3(mblk, 4), blk, GEMM_SMEM>>>(
            pg_src_hi, pg_src_lo, vp_h, vp_l, vp_b + (size_t)i * 256, vp_b + (size_t)i * 256, 256,
            pg_val, nullptr, nullptr, MROWS, 256, 256);
        // [offsets | aw] = q @ [so_w | aw_w] + [so_b | aw_b]  (N=384 fused)
        mma_gemm<false, 0><<<dim3(mblk, 6), blk, GEMM_SMEM>>>(
            pg_q_hi, pg_q_lo, sa_h, sa_l, so_b + (size_t)i * 256, aw_b + (size_t)i * 128, 256,
            pg_offaw, nullptr, nullptr, MROWS, 256, 384);
        // deformable sampling -> attn pair
        deform_kernel<<<deform_grid, 256>>>(pg_val, pg_offaw, pg_attn_hi, pg_attn_lo);
        // output proj
        mma_gemm<false, 0><<<dim3(mblk, 4), blk, GEMM_SMEM>>>(
            pg_attn_hi, pg_attn_lo, op_h, op_l, op_b + (size_t)i * 256, op_b + (size_t)i * 256, 256,
            pg_tmp, nullptr, nullptr, MROWS, 256, 256);
        // src = LN(src + attn_proj)  (no q emission)
        add_ln_kernel<<<ln_grid, 256>>>(pg_src, pg_tmp,
                                        n1_w + (size_t)i * DMODEL, n1_b + (size_t)i * DMODEL,
                                        nullptr, pg_src, pg_src_hi, pg_src_lo, nullptr, nullptr);
        // h = relu(src @ f1_w + f1_b)  (bf16 pair out)
        mma_gemm<true, 1><<<dim3(mblk, 16), blk, GEMM_SMEM>>>(
            pg_src_hi, pg_src_lo, f1_h, f1_l, f1_b + (size_t)i * DFFN, f1_b + (size_t)i * DFFN, DFFN,
            nullptr, pg_h_hi, pg_h_lo, MROWS, 256, DFFN);
        // tmp = h @ f2_w + f2_b
        mma_gemm<false, 0><<<dim3(mblk, 4), blk, GEMM_SMEM>>>(
            pg_h_hi, pg_h_lo, f2_h, f2_l, f2_b + (size_t)i * 256, f2_b + (size_t)i * 256, 256,
            pg_tmp, nullptr, nullptr, MROWS, 1024, 256);
        // src = LN(src + ffn), also emit q pair for next layer
        add_ln_kernel<<<ln_grid, 256>>>(pg_src, pg_tmp,
                                        n2_w + (size_t)i * DMODEL, n2_b + (size_t)i * DMODEL,
                                        pg_pos, pg_src, pg_src_hi, pg_src_lo, pg_q_hi, pg_q_lo);
    }

    write_out_kernel<<<(out_size + 255) / 256, 256>>>((float*)d_out, out_size);
}